// round 2
// baseline (speedup 1.0000x reference)
#include <cuda_runtime.h>
#include <cstdint>

#define THREADS 128
// smem layout (floats): slab[32*3*66]=6336 | wbuf[128*36]=4608 | Hsm[128*68]=8704
#define SLAB_F   6336
#define WBUF_F   4608
#define HSM_F    8704
#define SMEM_BYTES ((SLAB_F + WBUF_F + HSM_F) * 4)

__device__ __forceinline__ unsigned long long bcast2(float v) {
    unsigned long long r;
    asm("mov.b64 %0, {%1, %1};" : "=l"(r) : "f"(v));
    return r;
}
__device__ __forceinline__ void unpack2(unsigned long long v, float& lo, float& hi) {
    asm("mov.b64 {%0, %1}, %2;" : "=f"(lo), "=f"(hi) : "l"(v));
}
__device__ __forceinline__ unsigned long long fma2(unsigned long long a,
                                                   unsigned long long b,
                                                   unsigned long long c) {
    unsigned long long d;
    asm("fma.rn.f32x2 %0, %1, %2, %3;" : "=l"(d) : "l"(a), "l"(b), "l"(c));
    return d;
}

__global__ __launch_bounds__(THREADS)
void lp_kernel(const float* __restrict__ z, const float* __restrict__ W1,
               const float* __restrict__ b1, const float* __restrict__ W2,
               const float* __restrict__ b2, float* __restrict__ out)
{
    extern __shared__ float smem[];
    float* slab = smem;                      // [k][r][c] = [32][3][66]
    float* wbuf = smem + SLAB_F;             // GEMM1: [32][132] ; GEMM2: [128][36]
    float* Hsm  = smem + SLAB_F + WBUF_F;    // [d][m] = [128][68]

    const int x0  = blockIdx.x * 64;
    const int y   = blockIdx.y;
    const int b   = blockIdx.z;
    const int tid = threadIdx.x;
    const int tm  = tid & 15;      // 16 m-groups of 4 pixels
    const int tn  = tid >> 4;      // 8 n-groups of 16 hidden
    const int tm4  = tm * 4;
    const int tn16 = tn * 16;

    const float* zb = z + ((size_t)b * 32) * 65536;

    // ---- stage z slab: rows y-1..y+1, cols x0-1..x0+64, zero-padded ----
    for (int idx = tid; idx < SLAB_F; idx += THREADS) {
        int k   = idx / 198;
        int rem = idx - k * 198;
        int r   = rem / 66;
        int c   = rem - r * 66;
        int yy = y - 1 + r;
        int xx = x0 - 1 + c;
        float v = 0.0f;
        if ((unsigned)yy < 256u && (unsigned)xx < 256u)
            v = zb[(size_t)k * 65536 + yy * 256 + xx];
        slab[idx] = v;
    }

    // ---- GEMM1: h[64 px][128 hid], K = 32 ch * 8 taps (center skipped) ----
    unsigned long long acc[4][8];
    #pragma unroll
    for (int i = 0; i < 4; ++i)
        #pragma unroll
        for (int j = 0; j < 8; ++j) acc[i][j] = 0ULL;

    for (int ch = 0; ch < 8; ++ch) {        // 8 chunks of 4 channels
        __syncthreads();
        // stage W1 chunk transposed: wbuf[tt*132 + d] = W1[d*288 + k*9 + p]
        #pragma unroll
        for (int it = 0; it < 32; ++it) {
            int idx = it * THREADS + tid;   // 4096 elems, t-fastest for coalescing
            int d  = idx >> 5;
            int tt = idx & 31;
            int q  = tt & 7;
            int kk = tt >> 3;
            int p  = q + (q >= 4);          // skip center tap (p==4)
            wbuf[tt * 132 + d] = W1[d * 288 + (ch * 4 + kk) * 9 + p];
        }
        __syncthreads();

        #pragma unroll
        for (int kk = 0; kk < 4; ++kk) {
            const float* sk = slab + (ch * 4 + kk) * 198 + tm4;
            #pragma unroll
            for (int q = 0; q < 8; ++q) {
                const int p  = q + (q >= 4);
                const int di = p / 3, dj = p % 3;
                const float* ar = sk + di * 66 + dj;
                unsigned long long A[4];
                A[0] = bcast2(ar[0]);
                A[1] = bcast2(ar[1]);
                A[2] = bcast2(ar[2]);
                A[3] = bcast2(ar[3]);
                const ulonglong2* wr =
                    (const ulonglong2*)(wbuf + (kk * 8 + q) * 132 + tn16);
                unsigned long long Wp[8];
                {
                    ulonglong2 t0 = wr[0]; Wp[0] = t0.x; Wp[1] = t0.y;
                    ulonglong2 t1 = wr[1]; Wp[2] = t1.x; Wp[3] = t1.y;
                    ulonglong2 t2 = wr[2]; Wp[4] = t2.x; Wp[5] = t2.y;
                    ulonglong2 t3 = wr[3]; Wp[6] = t3.x; Wp[7] = t3.y;
                }
                #pragma unroll
                for (int i = 0; i < 4; ++i)
                    #pragma unroll
                    for (int j = 0; j < 8; ++j)
                        acc[i][j] = fma2(A[i], Wp[j], acc[i][j]);
            }
        }
    }

    // ---- bias + ReLU, write H transposed [d][m] ----
    float bias1[16];
    #pragma unroll
    for (int j = 0; j < 16; ++j) bias1[j] = __ldg(&b1[tn16 + j]);

    #pragma unroll
    for (int i = 0; i < 4; ++i) {
        #pragma unroll
        for (int j = 0; j < 8; ++j) {
            float h0, h1;
            unpack2(acc[i][j], h0, h1);
            h0 = fmaxf(h0 + bias1[2 * j], 0.0f);
            h1 = fmaxf(h1 + bias1[2 * j + 1], 0.0f);
            int d0 = tn16 + 2 * j;
            Hsm[d0 * 68 + tm4 + i]       = h0;
            Hsm[(d0 + 1) * 68 + tm4 + i] = h1;
        }
    }
    __syncthreads();  // H ready; wbuf free for W2

    // stage W2 transposed: wbuf[t*36 + n] = W2[n*128 + t]
    #pragma unroll
    for (int it = 0; it < 32; ++it) {
        int idx = it * THREADS + tid;       // 4096 elems, t-fastest
        int n = idx >> 7;
        int t = idx & 127;
        wbuf[t * 36 + n] = W2[n * 128 + t];
    }
    __syncthreads();

    // ---- GEMM2: logits[64 px][32], K = 128 ----
    unsigned long long acc2[4][2];
    #pragma unroll
    for (int i = 0; i < 4; ++i) { acc2[i][0] = 0ULL; acc2[i][1] = 0ULL; }

    const int tn4 = tn * 4;
    #pragma unroll 8
    for (int t = 0; t < 128; ++t) {
        const float4 av = *(const float4*)(Hsm + t * 68 + tm4);
        const ulonglong2 bv = *(const ulonglong2*)(wbuf + t * 36 + tn4);
        unsigned long long A[4];
        A[0] = bcast2(av.x); A[1] = bcast2(av.y);
        A[2] = bcast2(av.z); A[3] = bcast2(av.w);
        #pragma unroll
        for (int i = 0; i < 4; ++i) {
            acc2[i][0] = fma2(A[i], bv.x, acc2[i][0]);
            acc2[i][1] = fma2(A[i], bv.y, acc2[i][1]);
        }
    }

    // ---- bias + vectorized store ----
    float bz[4];
    #pragma unroll
    for (int c = 0; c < 4; ++c) bz[c] = __ldg(&b2[tn4 + c]);

    float r[4][4];  // [n][m]
    #pragma unroll
    for (int i = 0; i < 4; ++i) {
        float lo, hi;
        unpack2(acc2[i][0], lo, hi);
        r[0][i] = lo + bz[0];
        r[1][i] = hi + bz[1];
        unpack2(acc2[i][1], lo, hi);
        r[2][i] = lo + bz[2];
        r[3][i] = hi + bz[3];
    }
    #pragma unroll
    for (int n = 0; n < 4; ++n) {
        int nn = tn4 + n;
        float4 v = make_float4(r[n][0], r[n][1], r[n][2], r[n][3]);
        *(float4*)(out + (((size_t)b * 32 + nn) * 256 + y) * 256 + x0 + tm4) = v;
    }
}

extern "C" void kernel_launch(void* const* d_in, const int* in_sizes, int n_in,
                              void* d_out, int out_size) {
    const float* z  = (const float*)d_in[0];
    const float* W1 = (const float*)d_in[1];
    const float* b1 = (const float*)d_in[2];
    const float* W2 = (const float*)d_in[3];
    const float* b2 = (const float*)d_in[4];
    float* out = (float*)d_out;

    cudaFuncSetAttribute(lp_kernel, cudaFuncAttributeMaxDynamicSharedMemorySize,
                         SMEM_BYTES);
    dim3 grid(4, 256, 8);   // x-tiles, rows, batch
    dim3 block(THREADS);
    lp_kernel<<<grid, block, SMEM_BYTES>>>(z, W1, b1, W2, b2, out);
}

// round 3
// speedup vs baseline: 1.0027x; 1.0027x over previous
#include <cuda_runtime.h>
#include <cstdint>

#define THREADS 128
// smem layout (floats): slab[32*3*66]=6336 | wbuf[128*36]=4608 | Hsm[128*68]=8704
#define SLAB_F   6336
#define WBUF_F   4608
#define HSM_F    8704
#define SMEM_BYTES ((SLAB_F + WBUF_F + HSM_F) * 4)

__device__ __forceinline__ unsigned long long bcast2(float v) {
    unsigned long long r;
    asm("mov.b64 %0, {%1, %1};" : "=l"(r) : "f"(v));
    return r;
}
__device__ __forceinline__ void unpack2(unsigned long long v, float& lo, float& hi) {
    asm("mov.b64 {%0, %1}, %2;" : "=f"(lo), "=f"(hi) : "l"(v));
}
__device__ __forceinline__ unsigned long long fma2(unsigned long long a,
                                                   unsigned long long b,
                                                   unsigned long long c) {
    unsigned long long d;
    asm("fma.rn.f32x2 %0, %1, %2, %3;" : "=l"(d) : "l"(a), "l"(b), "l"(c));
    return d;
}

__global__ __launch_bounds__(THREADS)
void lp_kernel(const float* __restrict__ z, const float* __restrict__ W1,
               const float* __restrict__ b1, const float* __restrict__ W2,
               const float* __restrict__ b2, float* __restrict__ out)
{
    extern __shared__ float smem[];
    float* slab = smem;                      // [k][r][c] = [32][3][66]
    float* wbuf = smem + SLAB_F;             // GEMM1: [32][132] ; GEMM2: [128][36]
    float* Hsm  = smem + SLAB_F + WBUF_F;    // [d][m] = [128][68]

    const int x0  = blockIdx.x * 64;
    const int y   = blockIdx.y;
    const int b   = blockIdx.z;
    const int tid = threadIdx.x;
    const int tm  = tid & 15;      // 16 m-groups of 4 pixels
    const int tn  = tid >> 4;      // 8 n-groups of 16 hidden
    const int tm4  = tm * 4;
    const int tn16 = tn * 16;

    const float* zb = z + ((size_t)b * 32) * 65536;

    // ---- stage z slab: rows y-1..y+1, cols x0-1..x0+64, zero-padded ----
    for (int idx = tid; idx < SLAB_F; idx += THREADS) {
        int k   = idx / 198;
        int rem = idx - k * 198;
        int r   = rem / 66;
        int c   = rem - r * 66;
        int yy = y - 1 + r;
        int xx = x0 - 1 + c;
        float v = 0.0f;
        if ((unsigned)yy < 256u && (unsigned)xx < 256u)
            v = zb[(size_t)k * 65536 + yy * 256 + xx];
        slab[idx] = v;
    }

    // ---- GEMM1: h[64 px][128 hid], K = 32 ch * 8 taps (center skipped) ----
    unsigned long long acc[4][8];
    #pragma unroll
    for (int i = 0; i < 4; ++i)
        #pragma unroll
        for (int j = 0; j < 8; ++j) acc[i][j] = 0ULL;

    for (int ch = 0; ch < 8; ++ch) {        // 8 chunks of 4 channels
        __syncthreads();
        // stage W1 chunk transposed: wbuf[tt*132 + d] = W1[d*288 + k*9 + p]
        #pragma unroll
        for (int it = 0; it < 32; ++it) {
            int idx = it * THREADS + tid;   // 4096 elems, t-fastest for coalescing
            int d  = idx >> 5;
            int tt = idx & 31;
            int q  = tt & 7;
            int kk = tt >> 3;
            int p  = q + (q >= 4);          // skip center tap (p==4)
            wbuf[tt * 132 + d] = W1[d * 288 + (ch * 4 + kk) * 9 + p];
        }
        __syncthreads();

        #pragma unroll
        for (int kk = 0; kk < 4; ++kk) {
            const float* sk = slab + (ch * 4 + kk) * 198 + tm4;
            #pragma unroll
            for (int q = 0; q < 8; ++q) {
                const int p  = q + (q >= 4);
                const int di = p / 3, dj = p % 3;
                const float* ar = sk + di * 66 + dj;
                unsigned long long A[4];
                A[0] = bcast2(ar[0]);
                A[1] = bcast2(ar[1]);
                A[2] = bcast2(ar[2]);
                A[3] = bcast2(ar[3]);
                const ulonglong2* wr =
                    (const ulonglong2*)(wbuf + (kk * 8 + q) * 132 + tn16);
                unsigned long long Wp[8];
                {
                    ulonglong2 t0 = wr[0]; Wp[0] = t0.x; Wp[1] = t0.y;
                    ulonglong2 t1 = wr[1]; Wp[2] = t1.x; Wp[3] = t1.y;
                    ulonglong2 t2 = wr[2]; Wp[4] = t2.x; Wp[5] = t2.y;
                    ulonglong2 t3 = wr[3]; Wp[6] = t3.x; Wp[7] = t3.y;
                }
                #pragma unroll
                for (int i = 0; i < 4; ++i)
                    #pragma unroll
                    for (int j = 0; j < 8; ++j)
                        acc[i][j] = fma2(A[i], Wp[j], acc[i][j]);
            }
        }
    }

    // ---- bias + ReLU, write H transposed [d][m] ----
    float bias1[16];
    #pragma unroll
    for (int j = 0; j < 16; ++j) bias1[j] = __ldg(&b1[tn16 + j]);

    #pragma unroll
    for (int i = 0; i < 4; ++i) {
        #pragma unroll
        for (int j = 0; j < 8; ++j) {
            float h0, h1;
            unpack2(acc[i][j], h0, h1);
            h0 = fmaxf(h0 + bias1[2 * j], 0.0f);
            h1 = fmaxf(h1 + bias1[2 * j + 1], 0.0f);
            int d0 = tn16 + 2 * j;
            Hsm[d0 * 68 + tm4 + i]       = h0;
            Hsm[(d0 + 1) * 68 + tm4 + i] = h1;
        }
    }
    __syncthreads();  // H ready; wbuf free for W2

    // stage W2 transposed: wbuf[t*36 + n] = W2[n*128 + t]
    #pragma unroll
    for (int it = 0; it < 32; ++it) {
        int idx = it * THREADS + tid;       // 4096 elems, t-fastest
        int n = idx >> 7;
        int t = idx & 127;
        wbuf[t * 36 + n] = W2[n * 128 + t];
    }
    __syncthreads();

    // ---- GEMM2: logits[64 px][32], K = 128 ----
    unsigned long long acc2[4][2];
    #pragma unroll
    for (int i = 0; i < 4; ++i) { acc2[i][0] = 0ULL; acc2[i][1] = 0ULL; }

    const int tn4 = tn * 4;
    #pragma unroll 8
    for (int t = 0; t < 128; ++t) {
        const float4 av = *(const float4*)(Hsm + t * 68 + tm4);
        const ulonglong2 bv = *(const ulonglong2*)(wbuf + t * 36 + tn4);
        unsigned long long A[4];
        A[0] = bcast2(av.x); A[1] = bcast2(av.y);
        A[2] = bcast2(av.z); A[3] = bcast2(av.w);
        #pragma unroll
        for (int i = 0; i < 4; ++i) {
            acc2[i][0] = fma2(A[i], bv.x, acc2[i][0]);
            acc2[i][1] = fma2(A[i], bv.y, acc2[i][1]);
        }
    }

    // ---- bias + vectorized store ----
    float bz[4];
    #pragma unroll
    for (int c = 0; c < 4; ++c) bz[c] = __ldg(&b2[tn4 + c]);

    float r[4][4];  // [n][m]
    #pragma unroll
    for (int i = 0; i < 4; ++i) {
        float lo, hi;
        unpack2(acc2[i][0], lo, hi);
        r[0][i] = lo + bz[0];
        r[1][i] = hi + bz[1];
        unpack2(acc2[i][1], lo, hi);
        r[2][i] = lo + bz[2];
        r[3][i] = hi + bz[3];
    }
    #pragma unroll
    for (int n = 0; n < 4; ++n) {
        int nn = tn4 + n;
        float4 v = make_float4(r[n][0], r[n][1], r[n][2], r[n][3]);
        *(float4*)(out + (((size_t)b * 32 + nn) * 256 + y) * 256 + x0 + tm4) = v;
    }
}

extern "C" void kernel_launch(void* const* d_in, const int* in_sizes, int n_in,
                              void* d_out, int out_size) {
    const float* z  = (const float*)d_in[0];
    const float* W1 = (const float*)d_in[1];
    const float* b1 = (const float*)d_in[2];
    const float* W2 = (const float*)d_in[3];
    const float* b2 = (const float*)d_in[4];
    float* out = (float*)d_out;

    cudaFuncSetAttribute(lp_kernel, cudaFuncAttributeMaxDynamicSharedMemorySize,
                         SMEM_BYTES);
    dim3 grid(4, 256, 8);   // x-tiles, rows, batch
    dim3 block(THREADS);
    lp_kernel<<<grid, block, SMEM_BYTES>>>(z, W1, b1, W2, b2, out);
}

// round 5
// speedup vs baseline: 2.3734x; 2.3670x over previous
#include <cuda_runtime.h>
#include <cuda_bf16.h>
#include <cstdint>

#define THREADS 256
#define NTILES  4096
#define GRID    148

// ---- smem layout (bytes); all matrix rows are 256 B (128 bf16) ----
#define OFF_AH    0u         // A / H hi  [128][128] bf16
#define OFF_AL    32768u     // A / H lo
#define OFF_W1    65536u     // + chunk*65536 + comp*32768  (4 x 32 KB)
#define OFF_W2    196608u    // + comp*8192                 (2 x 8 KB)
#define OFF_B1    212992u    // 128 f32
#define OFF_B2    213504u    // 32 f32
#define SMEM_TOTAL 213632u

__device__ __forceinline__ uint32_t smem_u32(const void* p) {
    uint32_t a;
    asm("{ .reg .u64 t; cvta.to.shared.u64 t, %1; cvt.u32.u64 %0, t; }"
        : "=r"(a) : "l"(p));
    return a;
}
// XOR-swizzled byte offset for element (row, k); row stride 256B, 16B chunks
// permuted by row&7 so ldmatrix (8 rows x 16B) is bank-conflict-free.
__device__ __forceinline__ uint32_t swz(int row, int k) {
    return (uint32_t)(row * 256 + ((((k >> 3) ^ (row & 7)) & 15) << 4) + (k & 7) * 2);
}
__device__ __forceinline__ void ldsm4(uint32_t r[4], uint32_t addr) {
    asm volatile("ldmatrix.sync.aligned.m8n8.x4.shared.b16 {%0,%1,%2,%3}, [%4];"
                 : "=r"(r[0]), "=r"(r[1]), "=r"(r[2]), "=r"(r[3]) : "r"(addr));
}
__device__ __forceinline__ void mma16816(float c[4], const uint32_t a[4],
                                         uint32_t b0, uint32_t b1) {
    asm volatile("mma.sync.aligned.m16n8k16.row.col.f32.bf16.bf16.f32 "
                 "{%0,%1,%2,%3}, {%4,%5,%6,%7}, {%8,%9}, {%0,%1,%2,%3};"
                 : "+f"(c[0]), "+f"(c[1]), "+f"(c[2]), "+f"(c[3])
                 : "r"(a[0]), "r"(a[1]), "r"(a[2]), "r"(a[3]), "r"(b0), "r"(b1));
}
__device__ __forceinline__ uint32_t packsplit(float h0, float h1, uint32_t& lo) {
    __nv_bfloat162 th = __floats2bfloat162_rn(h0, h1);
    __nv_bfloat162 tl = __floats2bfloat162_rn(h0 - __bfloat162float(th.x),
                                              h1 - __bfloat162float(th.y));
    lo = *(uint32_t*)&tl;
    return *(uint32_t*)&th;
}

__global__ __launch_bounds__(THREADS, 1)
void lp_mma(const float* __restrict__ z, const float* __restrict__ W1,
            const float* __restrict__ b1, const float* __restrict__ W2,
            const float* __restrict__ b2, float* __restrict__ out)
{
    extern __shared__ __align__(16) char smem[];
    const uint32_t sb = smem_u32(smem);
    const int tid  = threadIdx.x;
    const int w    = tid >> 5;
    const int lane = tid & 31;

    // ---------- one-time: stage W1 split (both chunks), W2 split, biases ----------
    for (int idx = tid; idx < 2 * 128 * 128; idx += THREADS) {
        int c = idx >> 14, d = (idx >> 7) & 127, k = idx & 127;
        int q = k >> 5, ch = k & 31;
        int p = c ? q + 5 : q;                  // skip center tap (p==4)
        float v = W1[d * 288 + ch * 9 + p];
        uint32_t lo, hi = packsplit(v, 0.0f, lo);
        uint32_t off = swz(d, k);
        *(__nv_bfloat16*)(smem + OFF_W1 + (uint32_t)c * 65536u + off) = *(__nv_bfloat16*)&hi;
        *(__nv_bfloat16*)(smem + OFF_W1 + (uint32_t)c * 65536u + 32768u + off) = *(__nv_bfloat16*)&lo;
    }
    for (int idx = tid; idx < 32 * 128; idx += THREADS) {
        int n = idx >> 7, t = idx & 127;
        float v = W2[n * 128 + t];
        uint32_t lo, hi = packsplit(v, 0.0f, lo);
        uint32_t off = swz(n, t);
        *(__nv_bfloat16*)(smem + OFF_W2 + off) = *(__nv_bfloat16*)&hi;
        *(__nv_bfloat16*)(smem + OFF_W2 + 8192u + off) = *(__nv_bfloat16*)&lo;
    }
    if (tid < 128) ((float*)(smem + OFF_B1))[tid] = b1[tid];
    if (tid < 32)  ((float*)(smem + OFF_B2))[tid] = b2[tid];
    __syncthreads();

    // ---------- per-warp tiling + ldmatrix lane addressing ----------
    const int mw = w & 3;        // layer-1 M slice: rows mw*32..+31
    const int nw = w >> 2;       // layer-1 N slice: cols nw*64..+63

    // A-fragment lane addressing (x4: rows lane&15, k-halves lane>>4)
    const int arow  = (lane & 15);
    const int kselA = lane >> 4;
    // B-fragment lane addressing (x4: n-octets, k-halves)
    const int brow  = ((lane >> 4) << 3) + (lane & 7);
    const int kselB = (lane >> 3) & 1;

    // layer-1 precomputed row bytes
    uint32_t rowA1[2], rowB1[4];
    #pragma unroll
    for (int mi = 0; mi < 2; ++mi) rowA1[mi] = (uint32_t)((mw * 32 + mi * 16 + arow) * 256);
    #pragma unroll
    for (int jq = 0; jq < 4; ++jq) rowB1[jq] = (uint32_t)((nw * 64 + jq * 16 + brow) * 256);
    const int xorA1 = (mw * 32 + arow) & 7;     // row&7 invariant under +16
    const int xorB1 = brow & 7;
    // layer-2
    const uint32_t rowA2 = (uint32_t)((w * 16 + arow) * 256);
    const int xorA2 = arow & 7;
    uint32_t rowB2[2];
    rowB2[0] = (uint32_t)(brow * 256);
    rowB2[1] = (uint32_t)((16 + brow) * 256);

    const float* b1s = (const float*)(smem + OFF_B1);
    const float* b2s = (const float*)(smem + OFF_B2);

    for (int t = blockIdx.x; t < NTILES; t += GRID) {
        const int x0 = (t & 1) * 128;
        const int y  = (t >> 1) & 255;
        const int b  = t >> 9;
        const float* zb = z + (size_t)b * 32 * 65536;

        float C[2][8][4];
        #pragma unroll
        for (int mi = 0; mi < 2; ++mi)
            #pragma unroll
            for (int jo = 0; jo < 8; ++jo)
                #pragma unroll
                for (int r = 0; r < 4; ++r) C[mi][jo][r] = 0.0f;

        #pragma unroll 1
        for (int c = 0; c < 2; ++c) {
            // ---- im2col staging of K-chunk c (bf16 split, swizzled) ----
            {
                const int m  = (w & 3) * 32 + lane;       // pixel row 0..127
                const int gb = (w >> 2) * 8;              // k-group base
                #pragma unroll
                for (int g2 = 0; g2 < 8; ++g2) {
                    int g   = gb + g2;                    // 0..15 (8 channels each)
                    int q   = g >> 2;
                    int ch0 = (g & 3) * 8;
                    int p   = c ? q + 5 : q;
                    int di  = p / 3, dj = p - di * 3;
                    int yy  = y + di - 1;
                    int xx  = x0 + m + dj - 1;
                    bool ok = ((unsigned)yy < 256u) && ((unsigned)xx < 256u);
                    const float* src = zb + (size_t)ch0 * 65536 + (ptrdiff_t)(yy * 256 + xx);
                    uint32_t hi4[4], lo4[4];
                    #pragma unroll
                    for (int i = 0; i < 4; ++i) {
                        float v0 = ok ? src[(2 * i) * 65536]     : 0.0f;
                        float v1 = ok ? src[(2 * i + 1) * 65536] : 0.0f;
                        hi4[i] = packsplit(v0, v1, lo4[i]);
                    }
                    uint32_t off = swz(m, g * 8);
                    *(uint4*)(smem + OFF_AH + off) = make_uint4(hi4[0], hi4[1], hi4[2], hi4[3]);
                    *(uint4*)(smem + OFF_AL + off) = make_uint4(lo4[0], lo4[1], lo4[2], lo4[3]);
                }
            }
            __syncthreads();

            // ---- layer-1 MMAs: 3 split passes (AhBh, AlBh, AhBl) x 8 K-steps ----
            #pragma unroll 1
            for (int ps = 0; ps < 3; ++ps) {
                const uint32_t Ab = sb + (ps == 1 ? OFF_AL : OFF_AH);
                const uint32_t Bb = sb + OFF_W1 + (uint32_t)c * 65536u +
                                    (ps == 2 ? 32768u : 0u);
                #pragma unroll
                for (int s = 0; s < 8; ++s) {
                    const uint32_t koffA = (uint32_t)(((2 * s + kselA) ^ xorA1) << 4);
                    const uint32_t koffB = (uint32_t)(((2 * s + kselB) ^ xorB1) << 4);
                    uint32_t a[2][4];
                    #pragma unroll
                    for (int mi = 0; mi < 2; ++mi) ldsm4(a[mi], Ab + rowA1[mi] + koffA);
                    uint32_t bf[4][4];
                    #pragma unroll
                    for (int jq = 0; jq < 4; ++jq) ldsm4(bf[jq], Bb + rowB1[jq] + koffB);
                    #pragma unroll
                    for (int mi = 0; mi < 2; ++mi)
                        #pragma unroll
                        for (int jo = 0; jo < 8; ++jo)
                            mma16816(C[mi][jo], a[mi],
                                     bf[jo >> 1][(jo & 1) * 2],
                                     bf[jo >> 1][(jo & 1) * 2 + 1]);
                }
            }
            __syncthreads();   // before restaging / H writes
        }

        // ---- epilogue 1: bias + ReLU + bf16 split -> H (reuses A buffers) ----
        #pragma unroll
        for (int mi = 0; mi < 2; ++mi) {
            #pragma unroll
            for (int jo = 0; jo < 8; ++jo) {
                int row0 = mw * 32 + mi * 16 + (lane >> 2);
                int n    = nw * 64 + jo * 8 + (lane & 3) * 2;
                uint32_t boff = (uint32_t)((((n >> 3) ^ (row0 & 7)) << 4) + (n & 7) * 2);
                float h0 = fmaxf(C[mi][jo][0] + b1s[n],     0.0f);
                float h1 = fmaxf(C[mi][jo][1] + b1s[n + 1], 0.0f);
                uint32_t lo, hi = packsplit(h0, h1, lo);
                *(uint32_t*)(smem + OFF_AH + row0 * 256 + boff) = hi;
                *(uint32_t*)(smem + OFF_AL + row0 * 256 + boff) = lo;
                int row1 = row0 + 8;
                uint32_t boff1 = (uint32_t)((((n >> 3) ^ (row1 & 7)) << 4) + (n & 7) * 2);
                float h2 = fmaxf(C[mi][jo][2] + b1s[n],     0.0f);
                float h3 = fmaxf(C[mi][jo][3] + b1s[n + 1], 0.0f);
                uint32_t lo2, hi2 = packsplit(h2, h3, lo2);
                *(uint32_t*)(smem + OFF_AH + row1 * 256 + boff1) = hi2;
                *(uint32_t*)(smem + OFF_AL + row1 * 256 + boff1) = lo2;
            }
        }
        __syncthreads();

        // ---- layer 2: M16 per warp, N=32, K=128, 3 passes ----
        float C2[4][4];
        #pragma unroll
        for (int jo = 0; jo < 4; ++jo)
            #pragma unroll
            for (int r = 0; r < 4; ++r) C2[jo][r] = 0.0f;

        #pragma unroll 1
        for (int ps = 0; ps < 3; ++ps) {
            const uint32_t Ab = sb + (ps == 1 ? OFF_AL : OFF_AH);
            const uint32_t Bb = sb + OFF_W2 + (ps == 2 ? 8192u : 0u);
            #pragma unroll
            for (int s = 0; s < 8; ++s) {
                const uint32_t koffA = (uint32_t)(((2 * s + kselA) ^ xorA2) << 4);
                const uint32_t koffB = (uint32_t)(((2 * s + kselB) ^ xorB1) << 4);
                uint32_t a[4];
                ldsm4(a, Ab + rowA2 + koffA);
                uint32_t bf[2][4];
                #pragma unroll
                for (int jq = 0; jq < 2; ++jq) ldsm4(bf[jq], Bb + rowB2[jq] + koffB);
                #pragma unroll
                for (int jo = 0; jo < 4; ++jo)
                    mma16816(C2[jo], a,
                             bf[jo >> 1][(jo & 1) * 2],
                             bf[jo >> 1][(jo & 1) * 2 + 1]);
            }
        }

        // ---- epilogue 2: bias + store ----
        {
            const int m0 = w * 16 + (lane >> 2);
            #pragma unroll
            for (int jo = 0; jo < 4; ++jo) {
                int n = jo * 8 + (lane & 3) * 2;
                float* p0 = out + ((size_t)(b * 32 + n)) * 65536 + y * 256 + x0;
                float* p1 = p0 + 65536;
                p0[m0]     = C2[jo][0] + b2s[n];
                p1[m0]     = C2[jo][1] + b2s[n + 1];
                p0[m0 + 8] = C2[jo][2] + b2s[n];
                p1[m0 + 8] = C2[jo][3] + b2s[n + 1];
            }
        }
        __syncthreads();   // before next tile overwrites H buffers
    }
}

extern "C" void kernel_launch(void* const* d_in, const int* in_sizes, int n_in,
                              void* d_out, int out_size) {
    const float* z  = (const float*)d_in[0];
    const float* W1 = (const float*)d_in[1];
    const float* b1 = (const float*)d_in[2];
    const float* W2 = (const float*)d_in[3];
    const float* b2 = (const float*)d_in[4];
    float* out = (float*)d_out;

    cudaFuncSetAttribute(lp_mma, cudaFuncAttributeMaxDynamicSharedMemorySize,
                         SMEM_TOTAL);
    lp_mma<<<GRID, THREADS, SMEM_TOTAL>>>(z, W1, b1, W2, b2, out);
}

// round 6
// speedup vs baseline: 2.5843x; 1.0888x over previous
#include <cuda_runtime.h>
#include <cuda_bf16.h>
#include <cstdint>

#define THREADS 256
#define NTILES  4096
#define GRID    148

// ---- smem layout (bytes) ----
#define OFF_BUF0  0u          // A chunk buf0: [hi 16K][lo 16K]; later H-hi (32K)
#define OFF_BUF1  32768u      // A chunk buf1; later H-lo
#define OFF_W1    65536u      // + comp*65536 : [128 d][256 k] bf16, 512B rows
#define OFF_W2    196608u     // + comp*8192  : [32 n][128 k] bf16, 256B rows
#define OFF_B1    212992u
#define OFF_B2    213504u
#define SMEM_TOTAL 213632u

__device__ __forceinline__ uint32_t smem_u32(const void* p) {
    uint32_t a;
    asm("{ .reg .u64 t; cvta.to.shared.u64 t, %1; cvt.u32.u64 %0, t; }"
        : "=r"(a) : "l"(p));
    return a;
}
// swizzled byte offsets (16B chunks XOR row&7)
__device__ __forceinline__ uint32_t swzA(int m, int k) {   // stride 128B, k<64
    return (uint32_t)(m * 128 + (((k >> 3) ^ (m & 7)) << 4) + (k & 7) * 2);
}
__device__ __forceinline__ uint32_t swzW1(int d, int k) {  // stride 512B, k<256
    return (uint32_t)(d * 512 + (((k >> 3) ^ (d & 7)) << 4) + (k & 7) * 2);
}
__device__ __forceinline__ uint32_t swzH(int r, int k) {   // stride 256B, k<128
    return (uint32_t)(r * 256 + (((k >> 3) ^ (r & 7)) << 4) + (k & 7) * 2);
}
__device__ __forceinline__ void ldsm4(uint32_t r[4], uint32_t addr) {
    asm volatile("ldmatrix.sync.aligned.m8n8.x4.shared.b16 {%0,%1,%2,%3}, [%4];"
                 : "=r"(r[0]), "=r"(r[1]), "=r"(r[2]), "=r"(r[3]) : "r"(addr));
}
__device__ __forceinline__ void mma16816(float c[4], const uint32_t a[4],
                                         uint32_t b0, uint32_t b1) {
    asm volatile("mma.sync.aligned.m16n8k16.row.col.f32.bf16.bf16.f32 "
                 "{%0,%1,%2,%3}, {%4,%5,%6,%7}, {%8,%9}, {%0,%1,%2,%3};"
                 : "+f"(c[0]), "+f"(c[1]), "+f"(c[2]), "+f"(c[3])
                 : "r"(a[0]), "r"(a[1]), "r"(a[2]), "r"(a[3]), "r"(b0), "r"(b1));
}
__device__ __forceinline__ uint32_t packsplit(float h0, float h1, uint32_t& lo) {
    __nv_bfloat162 th = __floats2bfloat162_rn(h0, h1);
    __nv_bfloat162 tl = __floats2bfloat162_rn(h0 - __bfloat162float(th.x),
                                              h1 - __bfloat162float(th.y));
    lo = *(uint32_t*)&tl;
    return *(uint32_t*)&th;
}
// prefetch one K-chunk (2 taps x 32 ch) of tile t into regs
__device__ __forceinline__ void ldg_chunk(float pf[32], const float* __restrict__ z,
                                          int t, int c, int m, int qsel) {
    int x0 = (t & 1) * 128, y = (t >> 1) & 255, b = t >> 9;
    int q  = 2 * c + qsel;
    int p  = q + (q >= 4);             // skip center tap
    int di = p / 3, dj = p - di * 3;
    int yy = y + di - 1, xx = x0 + m + dj - 1;
    bool ok = ((unsigned)yy < 256u) && ((unsigned)xx < 256u) && (t < NTILES);
    const float* src = z + (size_t)((unsigned)t >> 9) * 32 * 65536
                         + (ptrdiff_t)(yy * 256 + xx);
    (void)b;
    #pragma unroll
    for (int ch = 0; ch < 32; ++ch)
        pf[ch] = ok ? src[(size_t)ch * 65536] : 0.0f;
}
__device__ __forceinline__ void sts_chunk(char* smem, uint32_t bufoff,
                                          const float pf[32], int m, int qsel) {
    #pragma unroll
    for (int c8 = 0; c8 < 4; ++c8) {
        uint32_t hi4[4], lo4[4];
        #pragma unroll
        for (int i = 0; i < 4; ++i)
            hi4[i] = packsplit(pf[c8 * 8 + 2 * i], pf[c8 * 8 + 2 * i + 1], lo4[i]);
        uint32_t off = swzA(m, qsel * 32 + c8 * 8);
        *(uint4*)(smem + bufoff + off)          = make_uint4(hi4[0], hi4[1], hi4[2], hi4[3]);
        *(uint4*)(smem + bufoff + 16384u + off) = make_uint4(lo4[0], lo4[1], lo4[2], lo4[3]);
    }
}

__global__ __launch_bounds__(THREADS, 1)
void lp_mma(const float* __restrict__ z, const float* __restrict__ W1,
            const float* __restrict__ b1, const float* __restrict__ W2,
            const float* __restrict__ b2, float* __restrict__ out)
{
    extern __shared__ __align__(16) char smem[];
    const uint32_t sb = smem_u32(smem);
    const int tid  = threadIdx.x;
    const int w    = tid >> 5;
    const int lane = tid & 31;

    // ---------- one-time weight staging ----------
    for (int idx = tid; idx < 128 * 256; idx += THREADS) {
        int d = idx >> 8, k = idx & 255;
        int q = k >> 5, ch = k & 31;
        int p = q + (q >= 4);
        float v = W1[d * 288 + ch * 9 + p];
        uint32_t lo, hi = packsplit(v, 0.0f, lo);
        uint32_t off = swzW1(d, k);
        *(__nv_bfloat16*)(smem + OFF_W1 + off)          = *(__nv_bfloat16*)&hi;
        *(__nv_bfloat16*)(smem + OFF_W1 + 65536u + off) = *(__nv_bfloat16*)&lo;
    }
    for (int idx = tid; idx < 32 * 128; idx += THREADS) {
        int n = idx >> 7, k = idx & 127;
        float v = W2[n * 128 + k];
        uint32_t lo, hi = packsplit(v, 0.0f, lo);
        uint32_t off = swzH(n, k);
        *(__nv_bfloat16*)(smem + OFF_W2 + off)         = *(__nv_bfloat16*)&hi;
        *(__nv_bfloat16*)(smem + OFF_W2 + 8192u + off) = *(__nv_bfloat16*)&lo;
    }
    if (tid < 128) ((float*)(smem + OFF_B1))[tid] = b1[tid];
    if (tid < 32)  ((float*)(smem + OFF_B2))[tid] = b2[tid];
    __syncthreads();

    // ---------- warp tiling / ldmatrix lane addressing ----------
    const int mw = w & 3;                 // layer-1 M slice (32 rows)
    const int nw = w >> 2;                // layer-1 N slice (64 cols)
    const int arow  = lane & 15;
    const int kselA = lane >> 4;
    const int brow  = ((lane >> 4) << 3) + (lane & 7);
    const int kselB = (lane >> 3) & 1;
    const int xorA  = arow & 7;
    const int xorB  = brow & 7;

    uint32_t rowA1[2], rowB1[4];
    #pragma unroll
    for (int mi = 0; mi < 2; ++mi) rowA1[mi] = (uint32_t)((mw * 32 + mi * 16 + arow) * 128);
    #pragma unroll
    for (int jq = 0; jq < 4; ++jq) rowB1[jq] = (uint32_t)((nw * 64 + jq * 16 + brow) * 512);
    const uint32_t rowA2 = (uint32_t)((w * 16 + arow) * 256);
    uint32_t rowB2[2] = { (uint32_t)(brow * 256), (uint32_t)((16 + brow) * 256) };

    const int sm  = tid & 127;            // staging pixel
    const int sq  = tid >> 7;             // staging tap-within-chunk

    const float* b1s = (const float*)(smem + OFF_B1);
    const float* b2s = (const float*)(smem + OFF_B2);

    float pf[32];
    ldg_chunk(pf, z, blockIdx.x, 0, sm, sq);   // prologue prefetch

    for (int t = blockIdx.x; t < NTILES; t += GRID) {
        const int x0 = (t & 1) * 128;
        const int y  = (t >> 1) & 255;
        const int b  = t >> 9;

        float C[2][8][4];
        #pragma unroll
        for (int mi = 0; mi < 2; ++mi)
            #pragma unroll
            for (int jo = 0; jo < 8; ++jo)
                #pragma unroll
                for (int r = 0; r < 4; ++r) C[mi][jo][r] = 0.0f;

        // ================= layer 1: 4 chunks of K=64, pipelined =================
        #pragma unroll 1
        for (int c = 0; c < 4; ++c) {
            sts_chunk(smem, (uint32_t)((c & 1) * 32768), pf, sm, sq);
            if (c < 3) ldg_chunk(pf, z, t, c + 1, sm, sq);
            __syncthreads();

            const uint32_t Ab = sb + (uint32_t)((c & 1) * 32768);
            const uint32_t Bh = sb + OFF_W1;
            const uint32_t Bl = sb + OFF_W1 + 65536u;
            #pragma unroll
            for (int s = 0; s < 4; ++s) {
                const uint32_t koA = (uint32_t)(((2 * s + kselA) ^ xorA) << 4);
                const uint32_t koB = (uint32_t)(((c * 8 + 2 * s + kselB) ^ xorB) << 4);
                uint32_t ah[2][4], al[2][4], bfr[4][4];
                #pragma unroll
                for (int mi = 0; mi < 2; ++mi) ldsm4(ah[mi], Ab + rowA1[mi] + koA);
                #pragma unroll
                for (int jq = 0; jq < 4; ++jq) ldsm4(bfr[jq], Bh + rowB1[jq] + koB);
                #pragma unroll
                for (int mi = 0; mi < 2; ++mi)
                    #pragma unroll
                    for (int jo = 0; jo < 8; ++jo)
                        mma16816(C[mi][jo], ah[mi],
                                 bfr[jo >> 1][(jo & 1) * 2], bfr[jo >> 1][(jo & 1) * 2 + 1]);
                #pragma unroll
                for (int mi = 0; mi < 2; ++mi) ldsm4(al[mi], Ab + 16384u + rowA1[mi] + koA);
                #pragma unroll
                for (int mi = 0; mi < 2; ++mi)
                    #pragma unroll
                    for (int jo = 0; jo < 8; ++jo)
                        mma16816(C[mi][jo], al[mi],
                                 bfr[jo >> 1][(jo & 1) * 2], bfr[jo >> 1][(jo & 1) * 2 + 1]);
                #pragma unroll
                for (int jq = 0; jq < 4; ++jq) ldsm4(bfr[jq], Bl + rowB1[jq] + koB);
                #pragma unroll
                for (int mi = 0; mi < 2; ++mi)
                    #pragma unroll
                    for (int jo = 0; jo < 8; ++jo)
                        mma16816(C[mi][jo], ah[mi],
                                 bfr[jo >> 1][(jo & 1) * 2], bfr[jo >> 1][(jo & 1) * 2 + 1]);
            }
        }
        __syncthreads();    // all layer-1 MMAs done; bufs free for H

        // prefetch chunk-0 of next tile (hidden behind epi1 + layer-2)
        ldg_chunk(pf, z, t + GRID, 0, sm, sq);

        // ---- epilogue 1: bias + ReLU + split -> H (buf0=hi, buf1=lo) ----
        #pragma unroll
        for (int mi = 0; mi < 2; ++mi) {
            #pragma unroll
            for (int jo = 0; jo < 8; ++jo) {
                int row0 = mw * 32 + mi * 16 + (lane >> 2);
                int n    = nw * 64 + jo * 8 + (lane & 3) * 2;
                float h0 = fmaxf(C[mi][jo][0] + b1s[n],     0.0f);
                float h1 = fmaxf(C[mi][jo][1] + b1s[n + 1], 0.0f);
                uint32_t lo, hi = packsplit(h0, h1, lo);
                uint32_t o0 = swzH(row0, n);
                *(uint32_t*)(smem + OFF_BUF0 + o0) = hi;
                *(uint32_t*)(smem + OFF_BUF1 + o0) = lo;
                float h2 = fmaxf(C[mi][jo][2] + b1s[n],     0.0f);
                float h3 = fmaxf(C[mi][jo][3] + b1s[n + 1], 0.0f);
                uint32_t lo2, hi2 = packsplit(h2, h3, lo2);
                uint32_t o1 = swzH(row0 + 8, n);
                *(uint32_t*)(smem + OFF_BUF0 + o1) = hi2;
                *(uint32_t*)(smem + OFF_BUF1 + o1) = lo2;
            }
        }
        __syncthreads();

        // ================= layer 2: M16/warp, N=32, K=128 =================
        float C2[4][4];
        #pragma unroll
        for (int jo = 0; jo < 4; ++jo)
            #pragma unroll
            for (int r = 0; r < 4; ++r) C2[jo][r] = 0.0f;

        #pragma unroll
        for (int s = 0; s < 8; ++s) {
            const uint32_t koA = (uint32_t)(((2 * s + kselA) ^ xorA) << 4);
            const uint32_t koB = (uint32_t)(((2 * s + kselB) ^ xorB) << 4);
            uint32_t ah[4], al[4], bfr[2][4];
            ldsm4(ah, sb + OFF_BUF0 + rowA2 + koA);
            #pragma unroll
            for (int jq = 0; jq < 2; ++jq) ldsm4(bfr[jq], sb + OFF_W2 + rowB2[jq] + koB);
            #pragma unroll
            for (int jo = 0; jo < 4; ++jo)
                mma16816(C2[jo], ah, bfr[jo >> 1][(jo & 1) * 2], bfr[jo >> 1][(jo & 1) * 2 + 1]);
            ldsm4(al, sb + OFF_BUF1 + rowA2 + koA);
            #pragma unroll
            for (int jo = 0; jo < 4; ++jo)
                mma16816(C2[jo], al, bfr[jo >> 1][(jo & 1) * 2], bfr[jo >> 1][(jo & 1) * 2 + 1]);
            #pragma unroll
            for (int jq = 0; jq < 2; ++jq) ldsm4(bfr[jq], sb + OFF_W2 + 8192u + rowB2[jq] + koB);
            #pragma unroll
            for (int jo = 0; jo < 4; ++jo)
                mma16816(C2[jo], ah, bfr[jo >> 1][(jo & 1) * 2], bfr[jo >> 1][(jo & 1) * 2 + 1]);
        }
        __syncthreads();    // layer-2 done; bufs free for next tile's STS

        // ---- epilogue 2: bias + store ----
        {
            const int m0 = w * 16 + (lane >> 2);
            #pragma unroll
            for (int jo = 0; jo < 4; ++jo) {
                int n = jo * 8 + (lane & 3) * 2;
                float* p0 = out + ((size_t)(b * 32 + n)) * 65536 + y * 256 + x0;
                float* p1 = p0 + 65536;
                p0[m0]     = C2[jo][0] + b2s[n];
                p1[m0]     = C2[jo][1] + b2s[n + 1];
                p0[m0 + 8] = C2[jo][2] + b2s[n];
                p1[m0 + 8] = C2[jo][3] + b2s[n + 1];
            }
        }
    }
}

extern "C" void kernel_launch(void* const* d_in, const int* in_sizes, int n_in,
                              void* d_out, int out_size) {
    const float* z  = (const float*)d_in[0];
    const float* W1 = (const float*)d_in[1];
    const float* b1 = (const float*)d_in[2];
    const float* W2 = (const float*)d_in[3];
    const float* b2 = (const float*)d_in[4];
    float* out = (float*)d_out;

    cudaFuncSetAttribute(lp_mma, cudaFuncAttributeMaxDynamicSharedMemorySize,
                         SMEM_TOTAL);
    lp_mma<<<GRID, THREADS, SMEM_TOTAL>>>(z, W1, b1, W2, b2, out);
}